// round 9
// baseline (speedup 1.0000x reference)
#include <cuda_runtime.h>
#include <cstdint>

#define S_MAX   2146592
#define TPB     256
#define TILE    1024
#define ROWS    (TILE / TPB)
#define EPS_F   1e-8f

// ---------------- zeroed-each-launch accumulator block (one memset node) ----------------
struct Accum {
    unsigned hists[4][256];
    double   base[4];
    double   rsum[4];
    int      n, rn;
    unsigned ctr[8];       // work-stealing counters, one per phase
    unsigned count, gen;   // grid barrier state
};
__device__ Accum    g_acc;
__device__ unsigned g_resbits[S_MAX];

// ---------------- software grid barrier (all blocks co-resident by construction) ----------------
__device__ __forceinline__ void grid_sync(int nb) {
    __syncthreads();
    if (threadIdx.x == 0) {
        volatile unsigned* vgen = (volatile unsigned*)&g_acc.gen;
        __threadfence();
        unsigned gen = *vgen;
        if (atomicAdd(&g_acc.count, 1u) == (unsigned)nb - 1u) {
            g_acc.count = 0u;
            __threadfence();
            *vgen = gen + 1u;
        } else {
            while (*vgen == gen) __nanosleep(40);
        }
        __threadfence();
    }
    __syncthreads();
}

// ---------------- mask accessor (format decided at runtime) ----------------
__device__ __forceinline__ bool mask_at(const void* m, int j, int mode) {
    if (mode == 0) return ((const unsigned char*)m)[j] != 0;
    if (mode == 1) return ((const int*)m)[j] != 0;
    return ((const float*)m)[j] != 0.0f;
}

__device__ __forceinline__ void affine_fit(double n, double sp, double sg,
                                           double spp, double spg,
                                           double& s, double& b) {
    double det = spp * n - sp * sp;
    if (fabs(det) >= 1e-8) {
        s = (spg * n - sp * sg) / det;
        b = (spp * sg - sp * spg) / det;
    } else {
        s = spg / fmax(spp, 1e-8);
        b = 0.0;
    }
}

// steal one TILE at a time for phase `ph`; BODY may contain commas (variadic)
#define STEAL_LOOP(ph, ntiles, ...) do {                                    \
    for (;;) {                                                              \
        if (t == 0) s_tile = (int)atomicAdd(&g_acc.ctr[ph], 1u);            \
        __syncthreads();                                                    \
        int tile_ = s_tile;                                                 \
        __syncthreads();                                                    \
        if (tile_ >= (ntiles)) break;                                       \
        int tbase_ = tile_ * TILE;                                          \
        _Pragma("unroll")                                                   \
        for (int e_ = 0; e_ < ROWS; e_++) {                                 \
            int j = tbase_ + e_ * TPB + t;                                  \
            if (j < S) { __VA_ARGS__ }                                      \
        }                                                                   \
    }                                                                       \
} while (0)

// ---------------- one persistent kernel: the whole pipeline ----------------
__global__ void __launch_bounds__(TPB) k_fused(
    const float* __restrict__ pred, const float* __restrict__ gt,
    const void* __restrict__ mask, float* __restrict__ out,
    int S, int out_size, int NB)
{
    __shared__ unsigned s_hist[256];
    __shared__ unsigned s_cls[4];
    __shared__ unsigned s_bin;
    __shared__ int      s_krem;
    __shared__ int      s_tile;

    const int t = threadIdx.x;
    const int lane = t & 31;
    const int ntiles = (S + TILE - 1) / TILE;

    // ---- phase 0: redundant per-block mask-format detect (word loads, L2-resident)
    int mode;
    {
        unsigned c0 = 0, c1 = 0, c2 = 0, c3 = 0;
        const unsigned* m32 = (const unsigned*)mask;
        int nw = (S < 65536 ? S : 65536) >> 2;
        for (int i = t; i < nw; i += TPB) {
            unsigned w = m32[i];
            c0 += (w & 0x000000FFu) ? 1u : 0u;
            c1 += (w & 0x0000FF00u) ? 1u : 0u;
            c2 += (w & 0x00FF0000u) ? 1u : 0u;
            c3 += (w & 0xFF000000u) ? 1u : 0u;
        }
        if (t < 4) s_cls[t] = 0u;
        __syncthreads();
        c0 = __reduce_add_sync(0xffffffffu, c0);
        c1 = __reduce_add_sync(0xffffffffu, c1);
        c2 = __reduce_add_sync(0xffffffffu, c2);
        c3 = __reduce_add_sync(0xffffffffu, c3);
        if (lane == 0) {
            if (c0) atomicAdd(&s_cls[0], c0);
            if (c1) atomicAdd(&s_cls[1], c1);
            if (c2) atomicAdd(&s_cls[2], c2);
            if (c3) atomicAdd(&s_cls[3], c3);
        }
        __syncthreads();
        if (s_cls[0] && s_cls[1])        mode = 0;  // u8: all byte offsets populated
        else if (s_cls[2] || s_cls[3])   mode = 2;  // f32 1.0f -> bytes 2,3
        else                             mode = 1;  // i32 0/1 -> byte 0 only
    }

    // ---- phase 1: base sums over all valid (work-stealing)
    {
        float sp = 0.f, sg = 0.f, spp = 0.f, spg = 0.f; int n = 0;
        STEAL_LOOP(0, ntiles,
            float p = pred[j]; float g = gt[j];
            if (mask_at(mask, j, mode) && g > EPS_F && p > EPS_F) {
                n++; sp += p; sg += g;
                spp = fmaf(p, p, spp); spg = fmaf(p, g, spg);
            }
        );
#pragma unroll
        for (int o = 16; o; o >>= 1) {
            sp  += __shfl_down_sync(0xffffffffu, sp,  o);
            sg  += __shfl_down_sync(0xffffffffu, sg,  o);
            spp += __shfl_down_sync(0xffffffffu, spp, o);
            spg += __shfl_down_sync(0xffffffffu, spg, o);
        }
        n = __reduce_add_sync(0xffffffffu, n);
        if (lane == 0) {
            atomicAdd(&g_acc.base[0], (double)sp);  atomicAdd(&g_acc.base[1], (double)sg);
            atomicAdd(&g_acc.base[2], (double)spp); atomicAdd(&g_acc.base[3], (double)spg);
            atomicAdd(&g_acc.n, n);
        }
    }
    grid_sync(NB);   // B1

    // ---- base fit, redundant per thread
    const int n_valid = g_acc.n;
    float s0, b0;
    {
        double sd, bd;
        affine_fit((double)n_valid, g_acc.base[0], g_acc.base[1],
                   g_acc.base[2], g_acc.base[3], sd, bd);
        s0 = (float)sd; b0 = (float)bd;
    }
    int kremain = (n_valid - 1) / 2;   // lower median index
    unsigned prefix = 0u;

    // ---- phases 2-5: exact median via 4x radix-256 select on residual bits
#pragma unroll 1
    for (int pass = 0; pass < 4; pass++) {
        int shift = 24 - 8 * pass;
        s_hist[t] = 0u;
        __syncthreads();
        if (pass == 0) {
            STEAL_LOOP(1, ntiles,
                float p = pred[j]; float g = gt[j];
                bool v = mask_at(mask, j, mode) && (g > EPS_F) && (p > EPS_F);
                float r = fabsf(g - fmaf(s0, p, b0));
                unsigned bits = v ? __float_as_uint(r) : 0xFFFFFFFFu;
                g_resbits[j] = bits;
                atomicAdd(&s_hist[bits >> 24], 1u);
            );
        } else {
            unsigned himask = 0xFFFFFFFFu << (shift + 8);
            STEAL_LOOP(1 + pass, ntiles,
                unsigned b = g_resbits[j];
                if (((b ^ prefix) & himask) == 0u)
                    atomicAdd(&s_hist[(b >> shift) & 255u], 1u);
            );
        }
        __syncthreads();
        if (s_hist[t]) atomicAdd(&g_acc.hists[pass][t], s_hist[t]);
        grid_sync(NB);           // B2..B5: histogram complete
        // per-block redundant scan (identical integer results everywhere)
        s_hist[t] = g_acc.hists[pass][t];
        __syncthreads();
        if (t == 0) {
            long long rem = kremain;
            unsigned long long cum = 0;
            int bin = 255;
            for (int i = 0; i < 256; i++) {
                unsigned c = s_hist[i];
                if ((long long)(cum + c) > rem) { bin = i; break; }
                cum += c;
            }
            s_bin = (unsigned)bin;
            s_krem = (int)(rem - (long long)cum);
        }
        __syncthreads();
        prefix |= s_bin << shift;
        kremain = s_krem;
        __syncthreads();
    }
    const float th = __uint_as_float(prefix) * 1.5f;
    const unsigned th_bits = __float_as_uint(th);

    // ---- phase 6: refit on inliers of the base model (resbits encodes validity + |r|)
    {
        float sp = 0.f, sg = 0.f, spp = 0.f, spg = 0.f; int n = 0;
        STEAL_LOOP(5, ntiles,
            if (g_resbits[j] < th_bits) {     // nonneg-float bits are order-preserving
                float p = pred[j]; float g = gt[j];
                n++; sp += p; sg += g;
                spp = fmaf(p, p, spp); spg = fmaf(p, g, spg);
            }
        );
#pragma unroll
        for (int o = 16; o; o >>= 1) {
            sp  += __shfl_down_sync(0xffffffffu, sp,  o);
            sg  += __shfl_down_sync(0xffffffffu, sg,  o);
            spp += __shfl_down_sync(0xffffffffu, spp, o);
            spg += __shfl_down_sync(0xffffffffu, spg, o);
        }
        n = __reduce_add_sync(0xffffffffu, n);
        if (lane == 0) {
            atomicAdd(&g_acc.rsum[0], (double)sp);  atomicAdd(&g_acc.rsum[1], (double)sg);
            atomicAdd(&g_acc.rsum[2], (double)spp); atomicAdd(&g_acc.rsum[3], (double)spg);
            atomicAdd(&g_acc.rn, n);
        }
    }
    grid_sync(NB);   // B6

    // ---- final fit (redundant per thread) + output (work-stealing)
    float scale, shiftv;
    {
        double sd, bd;
        affine_fit((double)g_acc.rn, g_acc.rsum[0], g_acc.rsum[1],
                   g_acc.rsum[2], g_acc.rsum[3], sd, bd);
        bool use = g_acc.rn > 10;
        scale  = use ? (float)sd : s0;
        shiftv = use ? (float)bd : b0;
        scale = fminf(fmaxf(scale, 0.01f), 100.f);
    }
    STEAL_LOOP(6, ntiles,
        out[j] = fmaxf(fmaf(scale, pred[j], shiftv), 0.f);
    );
    if (blockIdx.x == 0 && t == 0) {
        if (S < out_size)     out[S] = scale;
        if (S + 1 < out_size) out[S + 1] = shiftv;
    }
}

// ---------------- launch ----------------
extern "C" void kernel_launch(void* const* d_in, const int* in_sizes, int n_in,
                              void* d_out, int out_size) {
    const float* pred = (const float*)d_in[0];
    const float* gt   = (const float*)d_in[1];
    const void*  mask = d_in[2];
    float* out = (float*)d_out;
    int S = in_sizes[0];

    // zero all accumulators + counters + barrier state (capturable memset node)
    void* accp = nullptr;
    cudaGetSymbolAddress(&accp, g_acc);
    cudaMemsetAsync(accp, 0, sizeof(Accum));

    // all-co-resident grid: occupancy-derived, deadlock-safe for the software barrier
    int dev = 0, nsm = 0, bpm = 0;
    cudaGetDevice(&dev);
    cudaDeviceGetAttribute(&nsm, cudaDevAttrMultiProcessorCount, dev);
    cudaOccupancyMaxActiveBlocksPerMultiprocessor(&bpm, k_fused, TPB, 0);
    if (nsm <= 0) nsm = 148;
    if (bpm <= 0) bpm = 1;
    int NB = nsm * bpm;

    k_fused<<<NB, TPB>>>(pred, gt, mask, out, S, out_size, NB);
}